// round 11
// baseline (speedup 1.0000x reference)
#include <cuda_runtime.h>
#include <cuda_bf16.h>
#include <cstdint>

// Problem constants
#define BB 64
#define SS 512
#define EE 256
#define HH 128
#define MM (BB * SS)          // 32768 rows
#define PAD 64                // padded neighbor-list width
#define PGRID 148             // persistent GEMM grid (<= SM count)

typedef unsigned long long ull;
typedef unsigned short u16;

// ---------------- device scratch --------------------------------------------
__device__ float g_Y[MM * HH];       // GEMM output h @ W^T (fp32)
__device__ u16   g_ahi[MM * EE];     // activation hi bf16 (layer1: 256 wide, else 128)
__device__ u16   g_alo[MM * EE];     // activation lo bf16
__device__ u16   g_whi[128 * 256 + 2 * 128 * 128];   // W1|W2|W3 hi bf16
__device__ u16   g_wlo[128 * 256 + 2 * 128 * 128];   // W1|W2|W3 lo bf16
__device__ u16   g_nbr[MM * PAD];    // neighbor lists, indices pre-scaled by 32
__device__ int   g_cnt[MM];          // neighbor count padded to multiple of 8
__device__ float g_dinv[MM];         // 1 / (deg + 1)

#define W2_OFF (128 * 256)
#define W3_OFF (128 * 256 + 128 * 128)

// ---------------- packed f32x2 helpers --------------------------------------
__device__ __forceinline__ void unpack2(ull v, float& x, float& y) {
    asm("mov.b64 {%0, %1}, %2;" : "=f"(x), "=f"(y) : "l"(v));
}
__device__ __forceinline__ void fadd2(ull& d, ull a) {
    asm("add.rn.f32x2 %0, %0, %1;" : "+l"(d) : "l"(a));
}

// ---------------- mma.sync / cp.async plumbing -------------------------------
__device__ __forceinline__ uint32_t smem_to_u32(const void* p) {
    uint32_t a;
    asm("{ .reg .u64 t; cvta.to.shared.u64 t, %1; cvt.u32.u64 %0, t; }" : "=r"(a) : "l"(p));
    return a;
}
__device__ __forceinline__ void ldsm4(uint32_t& r0, uint32_t& r1, uint32_t& r2, uint32_t& r3,
                                      uint32_t addr) {
    asm volatile("ldmatrix.sync.aligned.m8n8.x4.shared.b16 {%0,%1,%2,%3}, [%4];"
                 : "=r"(r0), "=r"(r1), "=r"(r2), "=r"(r3) : "r"(addr));
}
__device__ __forceinline__ void mma16816(float* c, const uint32_t* a, const uint32_t* b) {
    asm volatile("mma.sync.aligned.m16n8k16.row.col.f32.bf16.bf16.f32 "
                 "{%0,%1,%2,%3}, {%4,%5,%6,%7}, {%8,%9}, {%0,%1,%2,%3};"
                 : "+f"(c[0]), "+f"(c[1]), "+f"(c[2]), "+f"(c[3])
                 : "r"(a[0]), "r"(a[1]), "r"(a[2]), "r"(a[3]), "r"(b[0]), "r"(b[1]));
}
__device__ __forceinline__ void cp_async16(uint32_t dst, const void* src) {
    asm volatile("cp.async.cg.shared.global [%0], [%1], 16;" :: "r"(dst), "l"(src));
}
#define CP_COMMIT() asm volatile("cp.async.commit_group;" ::: "memory")
#define CP_WAIT0()  asm volatile("cp.async.wait_group 0;" ::: "memory")
#define CP_WAIT1()  asm volatile("cp.async.wait_group 1;" ::: "memory")

// bf16 hi/lo split packing
__device__ __forceinline__ uint2 bfpack(float4 v) {
    __nv_bfloat162 p0 = __floats2bfloat162_rn(v.x, v.y);
    __nv_bfloat162 p1 = __floats2bfloat162_rn(v.z, v.w);
    uint2 r; r.x = *(unsigned*)&p0; r.y = *(unsigned*)&p1; return r;
}
__device__ __forceinline__ float4 bfres(float4 v) {
    float4 r;
    r.x = v.x - __bfloat162float(__float2bfloat16_rn(v.x));
    r.y = v.y - __bfloat162float(__float2bfloat16_rn(v.y));
    r.z = v.z - __bfloat162float(__float2bfloat16_rn(v.z));
    r.w = v.w - __bfloat162float(__float2bfloat16_rn(v.w));
    return r;
}

// ---------------- 1) fused prep: embed+split | mask | weight-split | out init --
#define PREP_GRID (4096 + 4096 + 256 + 1)

__global__ void __launch_bounds__(256) prep_kernel(const int* __restrict__ sent,
                                                   const float4* __restrict__ emb4,
                                                   const float* __restrict__ adj,
                                                   const float* __restrict__ W1,
                                                   const float* __restrict__ W2,
                                                   const float* __restrict__ W3,
                                                   const float* __restrict__ bp,
                                                   float* __restrict__ out) {
    int blk = blockIdx.x;
    int t   = threadIdx.x;

    if (blk < 4096) {
#pragma unroll
        for (int h = 0; h < 2; h++) {
            int i = blk * 512 + h * 256 + t;
            int row = i >> 6;
            int c   = i & 63;
            int tok = sent[row];
            float4 v = emb4[(size_t)tok * 64 + c];
            ((uint2*)g_ahi)[(size_t)row * 64 + c] = bfpack(v);
            ((uint2*)g_alo)[(size_t)row * 64 + c] = bfpack(bfres(v));
        }
    } else if (blk < 8192) {
        int row  = (blk - 4096) * 8 + (t >> 5);
        int lane = t & 31;
        const float* a = adj + (size_t)row * SS;
        unsigned myw = 0;
#pragma unroll
        for (int j = 0; j < 16; j++) {
            unsigned m = __ballot_sync(0xFFFFFFFFu, a[j * 32 + lane] != 0.0f);
            if (lane == j) myw = m;
        }
        int c = (lane < 16) ? __popc(myw) : 0;
        int pre = c;
#pragma unroll
        for (int off = 1; off < 32; off <<= 1) {
            int n = __shfl_up_sync(0xFFFFFFFFu, pre, off);
            if (lane >= off) pre += n;
        }
        int excl  = pre - c;
        int total = __shfl_sync(0xFFFFFFFFu, pre, 15);

        u16* lst = g_nbr + (size_t)row * PAD;
        if (lane < 16) {
            unsigned m = myw;
            int o = excl;
            while (m) {
                int b = __ffs(m) - 1;
                m &= m - 1;
                if (o < PAD) lst[o] = (u16)((32 * lane + b) << 5);
                o++;
            }
        }
        if (lane == 0) {
            int tt = (total > PAD) ? PAD : total;
            int t8 = (tt + 7) & ~7;
            if (t8 > PAD) t8 = PAD;
            for (int i = tt; i < t8; i++) lst[i] = (u16)(512 << 5);
            g_cnt[row]  = t8;
            g_dinv[row] = 1.0f / (float)(total + 1);
        }
    } else if (blk < 8448) {
        int j = (blk - 8192) * 256 + t;       // 0..65535
        const float* src; int off;
        if (j < 32768)      { src = W1; off = j; }
        else if (j < 49152) { src = W2; off = j - 32768; }
        else                { src = W3; off = j - 49152; }
        float v = src[off];
        __nv_bfloat16 h = __float2bfloat16_rn(v);
        __nv_bfloat16 l = __float2bfloat16_rn(v - __bfloat162float(h));
        g_whi[j] = *(u16*)&h;
        g_wlo[j] = *(u16*)&l;
    } else {
        if (t < BB * 2) out[t] = bp[t & 1];
    }
}

// ---------------- 2) persistent HMMA GEMM: Y = A @ W^T ------------------------
// 512 threads = 16 warps per CTA. B (weights hi/lo, all k-chunks) resident in
// smem; A tiles double-buffered + prefetched. Kt=128: M-tile 128 (4Mx4N warps);
// Kt=256: M-tile 64 (2Mx8N warps). smem = 208896 B either way -> 1 CTA/SM.
#define LDAe   136                      // bf16 elements per row (272 B pitch)
#define BT     (128 * LDAe * 2)         // 34816 B: one B half (hi or lo) per chunk

template <int Kt, int MT>
struct GS {
    static constexpr int NCHUNK = Kt / 128;
    static constexpr int NTILE  = MM / MT;
    static constexpr int A_HALF = MT * LDAe * 2;   // one A half (hi or lo)
    static constexpr int A_BUF  = 2 * A_HALF;      // hi + lo
    static constexpr int A_BASE = NCHUNK * 2 * BT;
    static constexpr int TOTAL  = A_BASE + 2 * A_BUF;   // 208896 for both configs
    static constexpr int NW_N   = (MT == 128) ? 4 : 8;  // warp col bands
    static constexpr int NW_M   = 16 / NW_N;            // warp row bands (of 32)
    static constexpr int COLS   = 128 / NW_N;            // cols per warp (32/16)
    static constexpr int NT     = COLS / 8;              // n8 frags per warp (4/2)
    static constexpr int MAXT   = (NTILE + PGRID - 1) / PGRID;
};

template <int Kt, int MT>
__device__ __forceinline__ void issue_a(uint32_t sb_abuf, int tile, int chunk, int tid) {
    constexpr int A_HALF = MT * LDAe * 2;
    for (int i = tid; i < MT * 16; i += 512) {
        int r = i >> 4, ch = i & 15;
        uint32_t doff = (uint32_t)r * 272u + ch * 16;
        size_t src = ((size_t)tile * MT + r) * Kt + chunk * 128 + ch * 8;
        uint32_t dhi = sb_abuf + doff;
        uint32_t dlo = sb_abuf + (uint32_t)A_HALF + doff;
        cp_async16(dhi, g_ahi + src);
        cp_async16(dlo, g_alo + src);
    }
}

template <int Kt, int MT>
__global__ void __launch_bounds__(512, 1) pgemm_kernel(const u16* __restrict__ whi,
                                                       const u16* __restrict__ wlo) {
    using G = GS<Kt, MT>;
    extern __shared__ char smem[];
    uint32_t sb = smem_to_u32(smem);

    int tid = threadIdx.x;
    int wid = tid >> 5;
    int lane = tid & 31;
    int mi = wid % G::NW_M;        // M band (32 rows)
    int ni = wid / G::NW_M;        // N band (COLS cols)

    // static tile assignment
    int myT[G::MAXT]; int ntl = 0;
    for (int t = blockIdx.x; t < G::NTILE; t += PGRID) myT[ntl++] = t;
    int total_units = ntl * G::NCHUNK;

    // ---- prologue: stage all B chunks (resident for the whole kernel)
    for (int i = tid; i < G::NCHUNK * 2048; i += 512) {
        int c = i >> 11, r = (i >> 4) & 127, ch = i & 15;
        uint32_t doff = (uint32_t)r * 272u + ch * 16;
        size_t src = (size_t)r * Kt + c * 128 + ch * 8;
        cp_async16(sb + (uint32_t)(c * 2 + 0) * BT + doff, whi + src);
        cp_async16(sb + (uint32_t)(c * 2 + 1) * BT + doff, wlo + src);
    }
    CP_COMMIT();
    // ---- A unit 0
    issue_a<Kt, MT>(sb + G::A_BASE, myT[0], 0, tid);
    CP_COMMIT();

    int arow_l = (lane & 15);
    int acol_l = (lane >> 4) << 3;
    int brow_l = (lane & 7) + ((lane >> 4) << 3);
    int bcol_l = ((lane >> 3) & 1) << 3;

    float acc[2][G::NT][4];

    for (int u = 0; u < total_units; u++) {
        int buf = u & 1;
        bool more = (u + 1 < total_units);
        if (more) {
            int nu = u + 1;
            issue_a<Kt, MT>(sb + G::A_BASE + (uint32_t)(nu & 1) * G::A_BUF,
                            myT[nu / G::NCHUNK], nu % G::NCHUNK, tid);
            CP_COMMIT();
            CP_WAIT1();           // everything except the just-issued group
        } else {
            CP_WAIT0();
        }
        __syncthreads();

        int chunk = u % G::NCHUNK;
        if (chunk == 0) {
#pragma unroll
            for (int mt = 0; mt < 2; mt++)
#pragma unroll
                for (int nt = 0; nt < G::NT; nt++)
#pragma unroll
                    for (int q = 0; q < 4; q++) acc[mt][nt][q] = 0.0f;
        }

        uint32_t sb_ahi = sb + G::A_BASE + (uint32_t)buf * G::A_BUF;
        uint32_t sb_alo = sb_ahi + (uint32_t)G::A_HALF;
        uint32_t sb_bhi = sb + (uint32_t)(chunk * 2 + 0) * BT;
        uint32_t sb_blo = sb + (uint32_t)(chunk * 2 + 1) * BT;

#pragma unroll
        for (int ks = 0; ks < 8; ks++) {
            int k = ks * 16;
            uint32_t ahi[2][4], alo[2][4];
#pragma unroll
            for (int mt = 0; mt < 2; mt++) {
                uint32_t eoff = (uint32_t)((mi * 32 + mt * 16 + arow_l) * LDAe + k + acol_l) * 2;
                ldsm4(ahi[mt][0], ahi[mt][1], ahi[mt][2], ahi[mt][3], sb_ahi + eoff);
                ldsm4(alo[mt][0], alo[mt][1], alo[mt][2], alo[mt][3], sb_alo + eoff);
            }
            uint32_t bhi[G::NT][2], blo[G::NT][2];
#pragma unroll
            for (int t = 0; t < G::NT / 2; t++) {
                uint32_t eoff = (uint32_t)((ni * G::COLS + t * 16 + brow_l) * LDAe + k + bcol_l) * 2;
                ldsm4(bhi[2*t][0], bhi[2*t][1], bhi[2*t+1][0], bhi[2*t+1][1], sb_bhi + eoff);
                ldsm4(blo[2*t][0], blo[2*t][1], blo[2*t+1][0], blo[2*t+1][1], sb_blo + eoff);
            }
#pragma unroll
            for (int mt = 0; mt < 2; mt++)
#pragma unroll
                for (int nt = 0; nt < G::NT; nt++) {
                    mma16816(acc[mt][nt], ahi[mt], bhi[nt]);   // hi*hi
                    mma16816(acc[mt][nt], alo[mt], bhi[nt]);   // lo*hi
                    mma16816(acc[mt][nt], ahi[mt], blo[nt]);   // hi*lo
                }
        }

        if (chunk == G::NCHUNK - 1) {
            size_t aBase = (size_t)myT[u / G::NCHUNK] * MT;
#pragma unroll
            for (int mt = 0; mt < 2; mt++) {
                size_t row0 = aBase + mi * 32 + mt * 16 + (lane >> 2);
#pragma unroll
                for (int nt = 0; nt < G::NT; nt++) {
                    int col = ni * G::COLS + nt * 8 + ((lane & 3) << 1);
                    *(float2*)&g_Y[row0 * 128 + col]       = make_float2(acc[mt][nt][0], acc[mt][nt][1]);
                    *(float2*)&g_Y[(row0 + 8) * 128 + col] = make_float2(acc[mt][nt][2], acc[mt][nt][3]);
                }
            }
        }
        __syncthreads();
    }
}

// ---------------- 3) sparse aggregation + bias + deg + relu -------------------
// LAST=false: emit hi/lo bf16 into g_ahi/g_alo (128-wide) for the next GEMM.
// LAST=true : no activation write; fused max-pool + partial logits atomicAdd.
#define SM_HS_F2   (513 * 32)
#define SM_CNT_OFF (SM_HS_F2 * 8)
#define SM_LST_OFF (SM_CNT_OFF + 512 * 4)
#define AGG_SMEM   (SM_LST_OFF + 512 * PAD * 2)

template <bool LAST>
__global__ void __launch_bounds__(1024) agg_kernel(const float* __restrict__ bias,
                                                   const float* __restrict__ Wp,
                                                   float* __restrict__ out) {
    extern __shared__ char smem[];
    float2* hs   = (float2*)smem;
    int*    scnt = (int*)(smem + SM_CNT_OFF);
    u16*    sl   = (u16*)(smem + SM_LST_OFF);

    int b  = blockIdx.x;
    int ch = blockIdx.y;
    int tid = threadIdx.x;

    const float2* Y2 = (const float2*)g_Y;

    for (int i = tid; i < SS * 32; i += 1024) {
        int t = i >> 5, f = i & 31;
        hs[i] = Y2[((size_t)(b * SS + t)) * 64 + ch * 32 + f];
    }
    if (tid < 32) hs[SS * 32 + tid] = make_float2(0.0f, 0.0f);
    if (tid < SS) scnt[tid] = g_cnt[b * SS + tid];
    {
        const int4* src = (const int4*)(g_nbr + (size_t)b * SS * PAD);
        int4* dst = (int4*)sl;
        for (int i = tid; i < SS * PAD / 8; i += 1024) dst[i] = src[i];
    }
    __syncthreads();

    int lane = tid & 31, warp = tid >> 5;
    float2 bv = ((const float2*)bias)[ch * 32 + lane];
    float bx = 2.0f * bv.x, by = 2.0f * bv.y;
    const float2* hl = hs + lane;

    float mx = 0.0f, my = 0.0f;    // running feature max (LAST only; relu => >= 0)

    for (int s = warp; s < SS; s += 32) {
        int row = b * SS + s;
        ull a0 = *(const ull*)&hl[s * 32];
        ull a1 = 0, a2 = 0, a3 = 0, a4 = 0, a5 = 0, a6 = 0, a7 = 0;

        int n8 = scnt[s];
        const u16* L = sl + s * PAD;
        for (int k = 0; k < n8; k += 8) {
            int4 pk = *(const int4*)(L + k);
            int i0 = pk.x & 0xFFFF, i1 = ((unsigned)pk.x) >> 16;
            int i2 = pk.y & 0xFFFF, i3 = ((unsigned)pk.y) >> 16;
            int i4 = pk.z & 0xFFFF, i5 = ((unsigned)pk.z) >> 16;
            int i6 = pk.w & 0xFFFF, i7 = ((unsigned)pk.w) >> 16;
            ull v0 = *(const ull*)&hl[i0];
            ull v1 = *(const ull*)&hl[i1];
            ull v2 = *(const ull*)&hl[i2];
            ull v3 = *(const ull*)&hl[i3];
            ull v4 = *(const ull*)&hl[i4];
            ull v5 = *(const ull*)&hl[i5];
            ull v6 = *(const ull*)&hl[i6];
            ull v7 = *(const ull*)&hl[i7];
            fadd2(a0, v0); fadd2(a1, v1); fadd2(a2, v2); fadd2(a3, v3);
            fadd2(a4, v4); fadd2(a5, v5); fadd2(a6, v6); fadd2(a7, v7);
        }
        fadd2(a0, a1); fadd2(a2, a3); fadd2(a4, a5); fadd2(a6, a7);
        fadd2(a0, a2); fadd2(a4, a6); fadd2(a0, a4);
        float sx, sy; unpack2(a0, sx, sy);
        float di = g_dinv[row];
        float ox = fmaxf((sx + bx) * di, 0.0f);
        float oy = fmaxf((sy + by) * di, 0.0f);
        if (LAST) {
            mx = fmaxf(mx, ox);
            my = fmaxf(my, oy);
        } else {
            size_t o = (size_t)row * 64 + ch * 32 + lane;   // u32 index (2 bf16)
            __nv_bfloat162 hp = __floats2bfloat162_rn(ox, oy);
            float lx = ox - __bfloat162float(__low2bfloat16(hp));
            float ly = oy - __bfloat162float(__high2bfloat16(hp));
            __nv_bfloat162 lp = __floats2bfloat162_rn(lx, ly);
            ((unsigned*)g_ahi)[o] = *(unsigned*)&hp;
            ((unsigned*)g_alo)[o] = *(unsigned*)&lp;
        }
    }

    if (LAST) {
        __syncthreads();
        float* red = (float*)(smem + SM_CNT_OFF);     // [32 warps][64 feats]
        red[warp * 64 + lane * 2]     = mx;
        red[warp * 64 + lane * 2 + 1] = my;
        __syncthreads();
        if (warp == 0) {
            float m0 = 0.0f, m1 = 0.0f;
#pragma unroll
            for (int w = 0; w < 32; w++) {
                m0 = fmaxf(m0, red[w * 64 + lane * 2]);
                m1 = fmaxf(m1, red[w * 64 + lane * 2 + 1]);
            }
            int j0 = ch * 64 + lane * 2;
            float p0 = m0 * Wp[0 * 128 + j0] + m1 * Wp[0 * 128 + j0 + 1];
            float p1 = m0 * Wp[1 * 128 + j0] + m1 * Wp[1 * 128 + j0 + 1];
#pragma unroll
            for (int off = 16; off > 0; off >>= 1) {
                p0 += __shfl_down_sync(0xFFFFFFFFu, p0, off);
                p1 += __shfl_down_sync(0xFFFFFFFFu, p1, off);
            }
            if (lane == 0) {
                atomicAdd(&out[b * 2 + 0], p0);
                atomicAdd(&out[b * 2 + 1], p1);
            }
        }
    }
}

// ---------------- launcher ---------------------------------------------------
extern "C" void kernel_launch(void* const* d_in, const int* in_sizes, int n_in,
                              void* d_out, int out_size) {
    const int*   sent = (const int*)  d_in[0];
    const float* adj  = (const float*)d_in[1];
    const float* emb  = (const float*)d_in[2];
    const float* W1   = (const float*)d_in[3];
    const float* b1   = (const float*)d_in[4];
    const float* W2   = (const float*)d_in[5];
    const float* b2   = (const float*)d_in[6];
    const float* W3   = (const float*)d_in[7];
    const float* b3   = (const float*)d_in[8];
    const float* Wp   = (const float*)d_in[9];
    const float* bp   = (const float*)d_in[10];
    float* out = (float*)d_out;

    cudaFuncSetAttribute(agg_kernel<false>, cudaFuncAttributeMaxDynamicSharedMemorySize, AGG_SMEM);
    cudaFuncSetAttribute(agg_kernel<true>,  cudaFuncAttributeMaxDynamicSharedMemorySize, AGG_SMEM);
    cudaFuncSetAttribute((const void*)pgemm_kernel<EE, 64>,
                         cudaFuncAttributeMaxDynamicSharedMemorySize, GS<EE, 64>::TOTAL);
    cudaFuncSetAttribute((const void*)pgemm_kernel<HH, 128>,
                         cudaFuncAttributeMaxDynamicSharedMemorySize, GS<HH, 128>::TOTAL);

    u16 *whi_d, *wlo_d;
    cudaGetSymbolAddress((void**)&whi_d, g_whi);
    cudaGetSymbolAddress((void**)&wlo_d, g_wlo);

    prep_kernel<<<PREP_GRID, 256>>>(sent, (const float4*)emb, adj, W1, W2, W3, bp, out);

    pgemm_kernel<EE, 64><<<PGRID, 512, GS<EE, 64>::TOTAL>>>(whi_d, wlo_d);
    agg_kernel<false><<<dim3(BB, 2), 1024, AGG_SMEM>>>(b1, nullptr, nullptr);

    pgemm_kernel<HH, 128><<<PGRID, 512, GS<HH, 128>::TOTAL>>>(whi_d + W2_OFF, wlo_d + W2_OFF);
    agg_kernel<false><<<dim3(BB, 2), 1024, AGG_SMEM>>>(b2, nullptr, nullptr);

    pgemm_kernel<HH, 128><<<PGRID, 512, GS<HH, 128>::TOTAL>>>(whi_d + W3_OFF, wlo_d + W3_OFF);
    agg_kernel<true><<<dim3(BB, 2), 1024, AGG_SMEM>>>(b3, Wp, out);
}

// round 12
// speedup vs baseline: 1.0024x; 1.0024x over previous
#include <cuda_runtime.h>
#include <cuda_bf16.h>
#include <cstdint>

// Problem constants
#define BB 64
#define SS 512
#define EE 256
#define HH 128
#define MM (BB * SS)          // 32768 rows
#define PAD 64                // padded neighbor-list width
#define PGRID 128             // persistent GEMM grid (tiles divide evenly)

typedef unsigned long long ull;
typedef unsigned short u16;

// ---------------- device scratch --------------------------------------------
__device__ float g_Y[MM * HH];       // GEMM output h @ W^T (fp32)
__device__ u16   g_ahi[MM * EE];     // activation hi bf16 (layer1: 256 wide, else 128)
__device__ u16   g_alo[MM * EE];     // activation lo bf16
__device__ u16   g_whi[128 * 256 + 2 * 128 * 128];   // W1|W2|W3 hi bf16
__device__ u16   g_wlo[128 * 256 + 2 * 128 * 128];   // W1|W2|W3 lo bf16
__device__ u16   g_nbr[MM * PAD];    // neighbor lists, indices pre-scaled by 32
__device__ int   g_cnt[MM];          // neighbor count padded to multiple of 8
__device__ float g_dinv[MM];         // 1 / (deg + 1)

#define W2_OFF (128 * 256)
#define W3_OFF (128 * 256 + 128 * 128)

// ---------------- packed f32x2 helpers --------------------------------------
__device__ __forceinline__ void unpack2(ull v, float& x, float& y) {
    asm("mov.b64 {%0, %1}, %2;" : "=f"(x), "=f"(y) : "l"(v));
}
__device__ __forceinline__ void fadd2(ull& d, ull a) {
    asm("add.rn.f32x2 %0, %0, %1;" : "+l"(d) : "l"(a));
}

// ---------------- mma.sync / cp.async plumbing -------------------------------
__device__ __forceinline__ uint32_t smem_to_u32(const void* p) {
    uint32_t a;
    asm("{ .reg .u64 t; cvta.to.shared.u64 t, %1; cvt.u32.u64 %0, t; }" : "=r"(a) : "l"(p));
    return a;
}
__device__ __forceinline__ void ldsm4(uint32_t& r0, uint32_t& r1, uint32_t& r2, uint32_t& r3,
                                      uint32_t addr) {
    asm volatile("ldmatrix.sync.aligned.m8n8.x4.shared.b16 {%0,%1,%2,%3}, [%4];"
                 : "=r"(r0), "=r"(r1), "=r"(r2), "=r"(r3) : "r"(addr));
}
__device__ __forceinline__ void mma16816(float* c, const uint32_t* a, const uint32_t* b) {
    asm volatile("mma.sync.aligned.m16n8k16.row.col.f32.bf16.bf16.f32 "
                 "{%0,%1,%2,%3}, {%4,%5,%6,%7}, {%8,%9}, {%0,%1,%2,%3};"
                 : "+f"(c[0]), "+f"(c[1]), "+f"(c[2]), "+f"(c[3])
                 : "r"(a[0]), "r"(a[1]), "r"(a[2]), "r"(a[3]), "r"(b[0]), "r"(b[1]));
}
__device__ __forceinline__ void cp_async16(uint32_t dst, const void* src) {
    asm volatile("cp.async.cg.shared.global [%0], [%1], 16;" :: "r"(dst), "l"(src));
}
#define CP_COMMIT() asm volatile("cp.async.commit_group;" ::: "memory")
#define CP_WAIT0()  asm volatile("cp.async.wait_group 0;" ::: "memory")
#define CP_WAIT1()  asm volatile("cp.async.wait_group 1;" ::: "memory")

// bf16 hi/lo split packing
__device__ __forceinline__ uint2 bfpack(float4 v) {
    __nv_bfloat162 p0 = __floats2bfloat162_rn(v.x, v.y);
    __nv_bfloat162 p1 = __floats2bfloat162_rn(v.z, v.w);
    uint2 r; r.x = *(unsigned*)&p0; r.y = *(unsigned*)&p1; return r;
}
__device__ __forceinline__ float4 bfres(float4 v) {
    float4 r;
    r.x = v.x - __bfloat162float(__float2bfloat16_rn(v.x));
    r.y = v.y - __bfloat162float(__float2bfloat16_rn(v.y));
    r.z = v.z - __bfloat162float(__float2bfloat16_rn(v.z));
    r.w = v.w - __bfloat162float(__float2bfloat16_rn(v.w));
    return r;
}

// ---------------- 1) fused prep: embed+split | mask | weight-split | out init --
#define PREP_GRID (4096 + 4096 + 256 + 1)

__global__ void __launch_bounds__(256) prep_kernel(const int* __restrict__ sent,
                                                   const float4* __restrict__ emb4,
                                                   const float* __restrict__ adj,
                                                   const float* __restrict__ W1,
                                                   const float* __restrict__ W2,
                                                   const float* __restrict__ W3,
                                                   const float* __restrict__ bp,
                                                   float* __restrict__ out) {
    int blk = blockIdx.x;
    int t   = threadIdx.x;

    if (blk < 4096) {
#pragma unroll
        for (int h = 0; h < 2; h++) {
            int i = blk * 512 + h * 256 + t;
            int row = i >> 6;
            int c   = i & 63;
            int tok = sent[row];
            float4 v = emb4[(size_t)tok * 64 + c];
            ((uint2*)g_ahi)[(size_t)row * 64 + c] = bfpack(v);
            ((uint2*)g_alo)[(size_t)row * 64 + c] = bfpack(bfres(v));
        }
    } else if (blk < 8192) {
        int row  = (blk - 4096) * 8 + (t >> 5);
        int lane = t & 31;
        const float* a = adj + (size_t)row * SS;
        unsigned myw = 0;
#pragma unroll
        for (int j = 0; j < 16; j++) {
            unsigned m = __ballot_sync(0xFFFFFFFFu, a[j * 32 + lane] != 0.0f);
            if (lane == j) myw = m;
        }
        int c = (lane < 16) ? __popc(myw) : 0;
        int pre = c;
#pragma unroll
        for (int off = 1; off < 32; off <<= 1) {
            int n = __shfl_up_sync(0xFFFFFFFFu, pre, off);
            if (lane >= off) pre += n;
        }
        int excl  = pre - c;
        int total = __shfl_sync(0xFFFFFFFFu, pre, 15);

        u16* lst = g_nbr + (size_t)row * PAD;
        if (lane < 16) {
            unsigned m = myw;
            int o = excl;
            while (m) {
                int b = __ffs(m) - 1;
                m &= m - 1;
                if (o < PAD) lst[o] = (u16)((32 * lane + b) << 5);
                o++;
            }
        }
        if (lane == 0) {
            int tt = (total > PAD) ? PAD : total;
            int t8 = (tt + 7) & ~7;
            if (t8 > PAD) t8 = PAD;
            for (int i = tt; i < t8; i++) lst[i] = (u16)(512 << 5);
            g_cnt[row]  = t8;
            g_dinv[row] = 1.0f / (float)(total + 1);
        }
    } else if (blk < 8448) {
        int j = (blk - 8192) * 256 + t;       // 0..65535
        const float* src; int off;
        if (j < 32768)      { src = W1; off = j; }
        else if (j < 49152) { src = W2; off = j - 32768; }
        else                { src = W3; off = j - 49152; }
        float v = src[off];
        __nv_bfloat16 h = __float2bfloat16_rn(v);
        __nv_bfloat16 l = __float2bfloat16_rn(v - __bfloat162float(h));
        g_whi[j] = *(u16*)&h;
        g_wlo[j] = *(u16*)&l;
    } else {
        if (t < BB * 2) out[t] = bp[t & 1];
    }
}

// ---------------- 2) persistent HMMA GEMM: Y = A @ W^T ------------------------
// 512 threads = 16 warps per CTA, PGRID=128 (even tile split). B resident in
// smem; A tiles double-buffered via cp.async; ldsm FRAGMENTS double-buffered
// across k-steps so mma(ks) overlaps ldsm(ks+1).
#define LDAe   136                      // bf16 elements per row (272 B pitch)
#define BT     (128 * LDAe * 2)         // 34816 B: one B half (hi or lo) per chunk

template <int Kt, int MT>
struct GS {
    static constexpr int NCHUNK = Kt / 128;
    static constexpr int NTILE  = MM / MT;
    static constexpr int A_HALF = MT * LDAe * 2;   // one A half (hi or lo)
    static constexpr int A_BUF  = 2 * A_HALF;      // hi + lo
    static constexpr int A_BASE = NCHUNK * 2 * BT;
    static constexpr int TOTAL  = A_BASE + 2 * A_BUF;   // 208896 for both configs
    static constexpr int NW_N   = (MT == 128) ? 4 : 8;  // warp col bands
    static constexpr int NW_M   = 16 / NW_N;            // warp row bands (of 32)
    static constexpr int COLS   = 128 / NW_N;            // cols per warp (32/16)
    static constexpr int NT     = COLS / 8;              // n8 frags per warp (4/2)
    static constexpr int MAXT   = (NTILE + PGRID - 1) / PGRID;
};

template <int NT>
struct Frag {
    uint32_t ahi[2][4], alo[2][4];
    uint32_t bhi[NT][2], blo[NT][2];
};

template <int NT>
__device__ __forceinline__ void ld_frags(Frag<NT>& f,
                                         uint32_t sb_ahi, uint32_t sb_alo,
                                         uint32_t sb_bhi, uint32_t sb_blo,
                                         int k, int mi, int ni,
                                         int arow_l, int acol_l, int brow_l, int bcol_l) {
#pragma unroll
    for (int mt = 0; mt < 2; mt++) {
        uint32_t eoff = (uint32_t)((mi * 32 + mt * 16 + arow_l) * LDAe + k + acol_l) * 2;
        ldsm4(f.ahi[mt][0], f.ahi[mt][1], f.ahi[mt][2], f.ahi[mt][3], sb_ahi + eoff);
        ldsm4(f.alo[mt][0], f.alo[mt][1], f.alo[mt][2], f.alo[mt][3], sb_alo + eoff);
    }
#pragma unroll
    for (int t = 0; t < NT / 2; t++) {
        uint32_t eoff = (uint32_t)((ni * (NT * 8) + t * 16 + brow_l) * LDAe + k + bcol_l) * 2;
        ldsm4(f.bhi[2*t][0], f.bhi[2*t][1], f.bhi[2*t+1][0], f.bhi[2*t+1][1], sb_bhi + eoff);
        ldsm4(f.blo[2*t][0], f.blo[2*t][1], f.blo[2*t+1][0], f.blo[2*t+1][1], sb_blo + eoff);
    }
}

template <int Kt, int MT>
__device__ __forceinline__ void issue_a(uint32_t sb_abuf, int tile, int chunk, int tid) {
    constexpr int A_HALF = MT * LDAe * 2;
    for (int i = tid; i < MT * 16; i += 512) {
        int r = i >> 4, ch = i & 15;
        uint32_t doff = (uint32_t)r * 272u + ch * 16;
        size_t src = ((size_t)tile * MT + r) * Kt + chunk * 128 + ch * 8;
        uint32_t dhi = sb_abuf + doff;
        uint32_t dlo = sb_abuf + (uint32_t)A_HALF + doff;
        cp_async16(dhi, g_ahi + src);
        cp_async16(dlo, g_alo + src);
    }
}

template <int Kt, int MT>
__global__ void __launch_bounds__(512, 1) pgemm_kernel(const u16* __restrict__ whi,
                                                       const u16* __restrict__ wlo) {
    using G = GS<Kt, MT>;
    extern __shared__ char smem[];
    uint32_t sb = smem_to_u32(smem);

    int tid = threadIdx.x;
    int wid = tid >> 5;
    int lane = tid & 31;
    int mi = wid % G::NW_M;        // M band (32 rows)
    int ni = wid / G::NW_M;        // N band (COLS cols)

    // static tile assignment (even split: NTILE % PGRID == 0)
    int myT[G::MAXT]; int ntl = 0;
    for (int t = blockIdx.x; t < G::NTILE; t += PGRID) myT[ntl++] = t;
    int total_units = ntl * G::NCHUNK;

    // ---- prologue: stage all B chunks (resident for the whole kernel)
    for (int i = tid; i < G::NCHUNK * 2048; i += 512) {
        int c = i >> 11, r = (i >> 4) & 127, ch = i & 15;
        uint32_t doff = (uint32_t)r * 272u + ch * 16;
        size_t src = (size_t)r * Kt + c * 128 + ch * 8;
        cp_async16(sb + (uint32_t)(c * 2 + 0) * BT + doff, whi + src);
        cp_async16(sb + (uint32_t)(c * 2 + 1) * BT + doff, wlo + src);
    }
    CP_COMMIT();
    // ---- A unit 0
    issue_a<Kt, MT>(sb + G::A_BASE, myT[0], 0, tid);
    CP_COMMIT();

    int arow_l = (lane & 15);
    int acol_l = (lane >> 4) << 3;
    int brow_l = (lane & 7) + ((lane >> 4) << 3);
    int bcol_l = ((lane >> 3) & 1) << 3;

    float acc[2][G::NT][4];

    for (int u = 0; u < total_units; u++) {
        int buf = u & 1;
        bool more = (u + 1 < total_units);
        if (more) {
            int nu = u + 1;
            issue_a<Kt, MT>(sb + G::A_BASE + (uint32_t)(nu & 1) * G::A_BUF,
                            myT[nu / G::NCHUNK], nu % G::NCHUNK, tid);
            CP_COMMIT();
            CP_WAIT1();           // everything except the just-issued group
        } else {
            CP_WAIT0();
        }
        __syncthreads();

        int chunk = u % G::NCHUNK;
        if (chunk == 0) {
#pragma unroll
            for (int mt = 0; mt < 2; mt++)
#pragma unroll
                for (int nt = 0; nt < G::NT; nt++)
#pragma unroll
                    for (int q = 0; q < 4; q++) acc[mt][nt][q] = 0.0f;
        }

        uint32_t sb_ahi = sb + G::A_BASE + (uint32_t)buf * G::A_BUF;
        uint32_t sb_alo = sb_ahi + (uint32_t)G::A_HALF;
        uint32_t sb_bhi = sb + (uint32_t)(chunk * 2 + 0) * BT;
        uint32_t sb_blo = sb + (uint32_t)(chunk * 2 + 1) * BT;

        // ---- 8 k16 steps, fragments double-buffered across steps
        Frag<G::NT> fr[2];
        ld_frags<G::NT>(fr[0], sb_ahi, sb_alo, sb_bhi, sb_blo, 0,
                        mi, ni, arow_l, acol_l, brow_l, bcol_l);
#pragma unroll
        for (int ks = 0; ks < 8; ks++) {
            int cur = ks & 1;
            if (ks < 7)
                ld_frags<G::NT>(fr[cur ^ 1], sb_ahi, sb_alo, sb_bhi, sb_blo, (ks + 1) * 16,
                                mi, ni, arow_l, acol_l, brow_l, bcol_l);
#pragma unroll
            for (int mt = 0; mt < 2; mt++)
#pragma unroll
                for (int nt = 0; nt < G::NT; nt++) {
                    mma16816(acc[mt][nt], fr[cur].ahi[mt], fr[cur].bhi[nt]);   // hi*hi
                    mma16816(acc[mt][nt], fr[cur].alo[mt], fr[cur].bhi[nt]);   // lo*hi
                    mma16816(acc[mt][nt], fr[cur].ahi[mt], fr[cur].blo[nt]);   // hi*lo
                }
        }

        if (chunk == G::NCHUNK - 1) {
            size_t aBase = (size_t)myT[u / G::NCHUNK] * MT;
#pragma unroll
            for (int mt = 0; mt < 2; mt++) {
                size_t row0 = aBase + mi * 32 + mt * 16 + (lane >> 2);
#pragma unroll
                for (int nt = 0; nt < G::NT; nt++) {
                    int col = ni * G::COLS + nt * 8 + ((lane & 3) << 1);
                    *(float2*)&g_Y[row0 * 128 + col]       = make_float2(acc[mt][nt][0], acc[mt][nt][1]);
                    *(float2*)&g_Y[(row0 + 8) * 128 + col] = make_float2(acc[mt][nt][2], acc[mt][nt][3]);
                }
            }
        }
        __syncthreads();
    }
}

// ---------------- 3) sparse aggregation + bias + deg + relu -------------------
// LAST=false: emit hi/lo bf16 into g_ahi/g_alo (128-wide) for the next GEMM.
// LAST=true : no activation write; fused max-pool + partial logits atomicAdd.
#define SM_HS_F2   (513 * 32)
#define SM_CNT_OFF (SM_HS_F2 * 8)
#define SM_LST_OFF (SM_CNT_OFF + 512 * 4)
#define AGG_SMEM   (SM_LST_OFF + 512 * PAD * 2)

template <bool LAST>
__global__ void __launch_bounds__(1024) agg_kernel(const float* __restrict__ bias,
                                                   const float* __restrict__ Wp,
                                                   float* __restrict__ out) {
    extern __shared__ char smem[];
    float2* hs   = (float2*)smem;
    int*    scnt = (int*)(smem + SM_CNT_OFF);
    u16*    sl   = (u16*)(smem + SM_LST_OFF);

    int b  = blockIdx.x;
    int ch = blockIdx.y;
    int tid = threadIdx.x;

    const float2* Y2 = (const float2*)g_Y;

    for (int i = tid; i < SS * 32; i += 1024) {
        int t = i >> 5, f = i & 31;
        hs[i] = Y2[((size_t)(b * SS + t)) * 64 + ch * 32 + f];
    }
    if (tid < 32) hs[SS * 32 + tid] = make_float2(0.0f, 0.0f);
    if (tid < SS) scnt[tid] = g_cnt[b * SS + tid];
    {
        const int4* src = (const int4*)(g_nbr + (size_t)b * SS * PAD);
        int4* dst = (int4*)sl;
        for (int i = tid; i < SS * PAD / 8; i += 1024) dst[i] = src[i];
    }
    __syncthreads();

    int lane = tid & 31, warp = tid >> 5;
    float2 bv = ((const float2*)bias)[ch * 32 + lane];
    float bx = 2.0f * bv.x, by = 2.0f * bv.y;
    const float2* hl = hs + lane;

    float mx = 0.0f, my = 0.0f;    // running feature max (LAST only; relu => >= 0)

    for (int s = warp; s < SS; s += 32) {
        int row = b * SS + s;
        ull a0 = *(const ull*)&hl[s * 32];
        ull a1 = 0, a2 = 0, a3 = 0, a4 = 0, a5 = 0, a6 = 0, a7 = 0;

        int n8 = scnt[s];
        const u16* L = sl + s * PAD;
        for (int k = 0; k < n8; k += 8) {
            int4 pk = *(const int4*)(L + k);
            int i0 = pk.x & 0xFFFF, i1 = ((unsigned)pk.x) >> 16;
            int i2 = pk.y & 0xFFFF, i3 = ((unsigned)pk.y) >> 16;
            int i4 = pk.z & 0xFFFF, i5 = ((unsigned)pk.z) >> 16;
            int i6 = pk.w & 0xFFFF, i7 = ((unsigned)pk.w) >> 16;
            ull v0 = *(const ull*)&hl[i0];
            ull v1 = *(const ull*)&hl[i1];
            ull v2 = *(const ull*)&hl[i2];
            ull v3 = *(const ull*)&hl[i3];
            ull v4 = *(const ull*)&hl[i4];
            ull v5 = *(const ull*)&hl[i5];
            ull v6 = *(const ull*)&hl[i6];
            ull v7 = *(const ull*)&hl[i7];
            fadd2(a0, v0); fadd2(a1, v1); fadd2(a2, v2); fadd2(a3, v3);
            fadd2(a4, v4); fadd2(a5, v5); fadd2(a6, v6); fadd2(a7, v7);
        }
        fadd2(a0, a1); fadd2(a2, a3); fadd2(a4, a5); fadd2(a6, a7);
        fadd2(a0, a2); fadd2(a4, a6); fadd2(a0, a4);
        float sx, sy; unpack2(a0, sx, sy);
        float di = g_dinv[row];
        float ox = fmaxf((sx + bx) * di, 0.0f);
        float oy = fmaxf((sy + by) * di, 0.0f);
        if (LAST) {
            mx = fmaxf(mx, ox);
            my = fmaxf(my, oy);
        } else {
            size_t o = (size_t)row * 64 + ch * 32 + lane;   // u32 index (2 bf16)
            __nv_bfloat162 hp = __floats2bfloat162_rn(ox, oy);
            float lx = ox - __bfloat162float(__low2bfloat16(hp));
            float ly = oy - __bfloat162float(__high2bfloat16(hp));
            __nv_bfloat162 lp = __floats2bfloat162_rn(lx, ly);
            ((unsigned*)g_ahi)[o] = *(unsigned*)&hp;
            ((unsigned*)g_alo)[o] = *(unsigned*)&lp;
        }
    }

    if (LAST) {
        __syncthreads();
        float* red = (float*)(smem + SM_CNT_OFF);     // [32 warps][64 feats]
        red[warp * 64 + lane * 2]     = mx;
        red[warp * 64 + lane * 2 + 1] = my;
        __syncthreads();
        if (warp == 0) {
            float m0 = 0.0f, m1 = 0.0f;
#pragma unroll
            for (int w = 0; w < 32; w++) {
                m0 = fmaxf(m0, red[w * 64 + lane * 2]);
                m1 = fmaxf(m1, red[w * 64 + lane * 2 + 1]);
            }
            int j0 = ch * 64 + lane * 2;
            float p0 = m0 * Wp[0 * 128 + j0] + m1 * Wp[0 * 128 + j0 + 1];
            float p1 = m0 * Wp[1 * 128 + j0] + m1 * Wp[1 * 128 + j0 + 1];
#pragma unroll
            for (int off = 16; off > 0; off >>= 1) {
                p0 += __shfl_down_sync(0xFFFFFFFFu, p0, off);
                p1 += __shfl_down_sync(0xFFFFFFFFu, p1, off);
            }
            if (lane == 0) {
                atomicAdd(&out[b * 2 + 0], p0);
                atomicAdd(&out[b * 2 + 1], p1);
            }
        }
    }
}

// ---------------- launcher ---------------------------------------------------
extern "C" void kernel_launch(void* const* d_in, const int* in_sizes, int n_in,
                              void* d_out, int out_size) {
    const int*   sent = (const int*)  d_in[0];
    const float* adj  = (const float*)d_in[1];
    const float* emb  = (const float*)d_in[2];
    const float* W1   = (const float*)d_in[3];
    const float* b1   = (const float*)d_in[4];
    const float* W2   = (const float*)d_in[5];
    const float* b2   = (const float*)d_in[6];
    const float* W3   = (const float*)d_in[7];
    const float* b3   = (const float*)d_in[8];
    const float* Wp   = (const float*)d_in[9];
    const float* bp   = (const float*)d_in[10];
    float* out = (float*)d_out;

    cudaFuncSetAttribute(agg_kernel<false>, cudaFuncAttributeMaxDynamicSharedMemorySize, AGG_SMEM);
    cudaFuncSetAttribute(agg_kernel<true>,  cudaFuncAttributeMaxDynamicSharedMemorySize, AGG_SMEM);
    cudaFuncSetAttribute((const void*)pgemm_kernel<EE, 64>,
                         cudaFuncAttributeMaxDynamicSharedMemorySize, GS<EE, 64>::TOTAL);
    cudaFuncSetAttribute((const void*)pgemm_kernel<HH, 128>,
                         cudaFuncAttributeMaxDynamicSharedMemorySize, GS<HH, 128>::TOTAL);

    u16 *whi_d, *wlo_d;
    cudaGetSymbolAddress((void**)&whi_d, g_whi);
    cudaGetSymbolAddress((void**)&wlo_d, g_wlo);

    prep_kernel<<<PREP_GRID, 256>>>(sent, (const float4*)emb, adj, W1, W2, W3, bp, out);

    pgemm_kernel<EE, 64><<<PGRID, 512, GS<EE, 64>::TOTAL>>>(whi_d, wlo_d);
    agg_kernel<false><<<dim3(BB, 2), 1024, AGG_SMEM>>>(b1, nullptr, nullptr);

    pgemm_kernel<HH, 128><<<PGRID, 512, GS<HH, 128>::TOTAL>>>(whi_d + W2_OFF, wlo_d + W2_OFF);
    agg_kernel<false><<<dim3(BB, 2), 1024, AGG_SMEM>>>(b2, nullptr, nullptr);

    pgemm_kernel<HH, 128><<<PGRID, 512, GS<HH, 128>::TOTAL>>>(whi_d + W3_OFF, wlo_d + W3_OFF);
    agg_kernel<true><<<dim3(BB, 2), 1024, AGG_SMEM>>>(b3, Wp, out);
}

// round 13
// speedup vs baseline: 1.0402x; 1.0377x over previous
#include <cuda_runtime.h>
#include <cuda_bf16.h>
#include <cstdint>

// Problem constants
#define BB 64
#define SS 512
#define EE 256
#define HH 128
#define MM (BB * SS)          // 32768 rows
#define PAD 64                // padded neighbor-list width
#define PGRID 128             // persistent GEMM grid (layer-1 GEMM)

typedef unsigned long long ull;
typedef unsigned short u16;

// ---------------- device scratch --------------------------------------------
__device__ float g_Y[MM * HH];       // layer-1 GEMM output (fp32)
__device__ u16   g_ahi[MM * EE];     // activations hi bf16: buf0 = [0,MM*128), buf1 = [MM*128,..)
__device__ u16   g_alo[MM * EE];     // activations lo bf16 (same split)
__device__ u16   g_whi[128 * 256 + 2 * 128 * 128];   // W1|W2|W3 hi bf16
__device__ u16   g_wlo[128 * 256 + 2 * 128 * 128];   // W1|W2|W3 lo bf16
__device__ u16   g_nbr[MM * PAD];    // neighbor lists, indices pre-scaled by 32
__device__ int   g_cnt[MM];          // neighbor count padded to multiple of 8
__device__ float g_dinv[MM];         // 1 / (deg + 1)

#define W2_OFF (128 * 256)
#define W3_OFF (128 * 256 + 128 * 128)

// ---------------- packed f32x2 helpers --------------------------------------
__device__ __forceinline__ void unpack2(ull v, float& x, float& y) {
    asm("mov.b64 {%0, %1}, %2;" : "=f"(x), "=f"(y) : "l"(v));
}
__device__ __forceinline__ void fadd2(ull& d, ull a) {
    asm("add.rn.f32x2 %0, %0, %1;" : "+l"(d) : "l"(a));
}

// ---------------- mma.sync / cp.async plumbing -------------------------------
__device__ __forceinline__ uint32_t smem_to_u32(const void* p) {
    uint32_t a;
    asm("{ .reg .u64 t; cvta.to.shared.u64 t, %1; cvt.u32.u64 %0, t; }" : "=r"(a) : "l"(p));
    return a;
}
__device__ __forceinline__ void ldsm4(uint32_t& r0, uint32_t& r1, uint32_t& r2, uint32_t& r3,
                                      uint32_t addr) {
    asm volatile("ldmatrix.sync.aligned.m8n8.x4.shared.b16 {%0,%1,%2,%3}, [%4];"
                 : "=r"(r0), "=r"(r1), "=r"(r2), "=r"(r3) : "r"(addr));
}
__device__ __forceinline__ void mma16816(float* c, const uint32_t* a, const uint32_t* b) {
    asm volatile("mma.sync.aligned.m16n8k16.row.col.f32.bf16.bf16.f32 "
                 "{%0,%1,%2,%3}, {%4,%5,%6,%7}, {%8,%9}, {%0,%1,%2,%3};"
                 : "+f"(c[0]), "+f"(c[1]), "+f"(c[2]), "+f"(c[3])
                 : "r"(a[0]), "r"(a[1]), "r"(a[2]), "r"(a[3]), "r"(b[0]), "r"(b[1]));
}
__device__ __forceinline__ void cp_async16(uint32_t dst, const void* src) {
    asm volatile("cp.async.cg.shared.global [%0], [%1], 16;" :: "r"(dst), "l"(src));
}
#define CP_COMMIT() asm volatile("cp.async.commit_group;" ::: "memory")
#define CP_WAIT0()  asm volatile("cp.async.wait_group 0;" ::: "memory")
#define CP_WAIT1()  asm volatile("cp.async.wait_group 1;" ::: "memory")

// bf16 hi/lo split packing
__device__ __forceinline__ uint2 bfpack(float4 v) {
    __nv_bfloat162 p0 = __floats2bfloat162_rn(v.x, v.y);
    __nv_bfloat162 p1 = __floats2bfloat162_rn(v.z, v.w);
    uint2 r; r.x = *(unsigned*)&p0; r.y = *(unsigned*)&p1; return r;
}
__device__ __forceinline__ float4 bfres(float4 v) {
    float4 r;
    r.x = v.x - __bfloat162float(__float2bfloat16_rn(v.x));
    r.y = v.y - __bfloat162float(__float2bfloat16_rn(v.y));
    r.z = v.z - __bfloat162float(__float2bfloat16_rn(v.z));
    r.w = v.w - __bfloat162float(__float2bfloat16_rn(v.w));
    return r;
}

// ---------------- 1) fused prep: embed+split | mask | weight-split | out init --
#define PREP_GRID (4096 + 4096 + 256 + 1)

__global__ void __launch_bounds__(256) prep_kernel(const int* __restrict__ sent,
                                                   const float4* __restrict__ emb4,
                                                   const float* __restrict__ adj,
                                                   const float* __restrict__ W1,
                                                   const float* __restrict__ W2,
                                                   const float* __restrict__ W3,
                                                   const float* __restrict__ bp,
                                                   float* __restrict__ out) {
    int blk = blockIdx.x;
    int t   = threadIdx.x;

    if (blk < 4096) {
#pragma unroll
        for (int h = 0; h < 2; h++) {
            int i = blk * 512 + h * 256 + t;
            int row = i >> 6;
            int c   = i & 63;
            int tok = sent[row];
            float4 v = emb4[(size_t)tok * 64 + c];
            ((uint2*)g_ahi)[(size_t)row * 64 + c] = bfpack(v);
            ((uint2*)g_alo)[(size_t)row * 64 + c] = bfpack(bfres(v));
        }
    } else if (blk < 8192) {
        int row  = (blk - 4096) * 8 + (t >> 5);
        int lane = t & 31;
        const float* a = adj + (size_t)row * SS;
        unsigned myw = 0;
#pragma unroll
        for (int j = 0; j < 16; j++) {
            unsigned m = __ballot_sync(0xFFFFFFFFu, a[j * 32 + lane] != 0.0f);
            if (lane == j) myw = m;
        }
        int c = (lane < 16) ? __popc(myw) : 0;
        int pre = c;
#pragma unroll
        for (int off = 1; off < 32; off <<= 1) {
            int n = __shfl_up_sync(0xFFFFFFFFu, pre, off);
            if (lane >= off) pre += n;
        }
        int excl  = pre - c;
        int total = __shfl_sync(0xFFFFFFFFu, pre, 15);

        u16* lst = g_nbr + (size_t)row * PAD;
        if (lane < 16) {
            unsigned m = myw;
            int o = excl;
            while (m) {
                int b = __ffs(m) - 1;
                m &= m - 1;
                if (o < PAD) lst[o] = (u16)((32 * lane + b) << 5);
                o++;
            }
        }
        if (lane == 0) {
            int tt = (total > PAD) ? PAD : total;
            int t8 = (tt + 7) & ~7;
            if (t8 > PAD) t8 = PAD;
            for (int i = tt; i < t8; i++) lst[i] = (u16)(512 << 5);
            g_cnt[row]  = t8;
            g_dinv[row] = 1.0f / (float)(total + 1);
        }
    } else if (blk < 8448) {
        int j = (blk - 8192) * 256 + t;       // 0..65535
        const float* src; int off;
        if (j < 32768)      { src = W1; off = j; }
        else if (j < 49152) { src = W2; off = j - 32768; }
        else                { src = W3; off = j - 49152; }
        float v = src[off];
        __nv_bfloat16 h = __float2bfloat16_rn(v);
        __nv_bfloat16 l = __float2bfloat16_rn(v - __bfloat162float(h));
        g_whi[j] = *(u16*)&h;
        g_wlo[j] = *(u16*)&l;
    } else {
        if (t < BB * 2) out[t] = bp[t & 1];
    }
}

// ---------------- 2) persistent HMMA GEMM (layer 1, K=256): Y = A @ W^T -------
#define LDAe   136                      // bf16 elements per row (272 B pitch)
#define BT     (128 * LDAe * 2)         // one B half (hi or lo) per chunk

template <int Kt, int MT>
struct GS {
    static constexpr int NCHUNK = Kt / 128;
    static constexpr int NTILE  = MM / MT;
    static constexpr int A_HALF = MT * LDAe * 2;
    static constexpr int A_BUF  = 2 * A_HALF;
    static constexpr int A_BASE = NCHUNK * 2 * BT;
    static constexpr int TOTAL  = A_BASE + 2 * A_BUF;
    static constexpr int NW_N   = (MT == 128) ? 4 : 8;
    static constexpr int NW_M   = 16 / NW_N;
    static constexpr int COLS   = 128 / NW_N;
    static constexpr int NT     = COLS / 8;
    static constexpr int MAXT   = (NTILE + PGRID - 1) / PGRID;
};

template <int Kt, int MT>
__device__ __forceinline__ void issue_a(uint32_t sb_abuf, int tile, int chunk, int tid) {
    constexpr int A_HALF = MT * LDAe * 2;
    for (int i = tid; i < MT * 16; i += 512) {
        int r = i >> 4, ch = i & 15;
        uint32_t doff = (uint32_t)r * 272u + ch * 16;
        size_t src = ((size_t)tile * MT + r) * Kt + chunk * 128 + ch * 8;
        uint32_t dhi = sb_abuf + doff;
        uint32_t dlo = sb_abuf + (uint32_t)A_HALF + doff;
        cp_async16(dhi, g_ahi + src);
        cp_async16(dlo, g_alo + src);
    }
}

template <int Kt, int MT>
__global__ void __launch_bounds__(512, 1) pgemm_kernel(const u16* __restrict__ whi,
                                                       const u16* __restrict__ wlo) {
    using G = GS<Kt, MT>;
    extern __shared__ char smem[];
    uint32_t sb = smem_to_u32(smem);

    int tid = threadIdx.x;
    int wid = tid >> 5;
    int lane = tid & 31;
    int mi = wid % G::NW_M;
    int ni = wid / G::NW_M;

    int myT[G::MAXT]; int ntl = 0;
    for (int t = blockIdx.x; t < G::NTILE; t += PGRID) myT[ntl++] = t;
    int total_units = ntl * G::NCHUNK;

    for (int i = tid; i < G::NCHUNK * 2048; i += 512) {
        int c = i >> 11, r = (i >> 4) & 127, ch = i & 15;
        uint32_t doff = (uint32_t)r * 272u + ch * 16;
        size_t src = (size_t)r * Kt + c * 128 + ch * 8;
        cp_async16(sb + (uint32_t)(c * 2 + 0) * BT + doff, whi + src);
        cp_async16(sb + (uint32_t)(c * 2 + 1) * BT + doff, wlo + src);
    }
    CP_COMMIT();
    issue_a<Kt, MT>(sb + G::A_BASE, myT[0], 0, tid);
    CP_COMMIT();

    int arow_l = (lane & 15);
    int acol_l = (lane >> 4) << 3;
    int brow_l = (lane & 7) + ((lane >> 4) << 3);
    int bcol_l = ((lane >> 3) & 1) << 3;

    float acc[2][G::NT][4];

    for (int u = 0; u < total_units; u++) {
        int buf = u & 1;
        bool more = (u + 1 < total_units);
        if (more) {
            int nu = u + 1;
            issue_a<Kt, MT>(sb + G::A_BASE + (uint32_t)(nu & 1) * G::A_BUF,
                            myT[nu / G::NCHUNK], nu % G::NCHUNK, tid);
            CP_COMMIT();
            CP_WAIT1();
        } else {
            CP_WAIT0();
        }
        __syncthreads();

        int chunk = u % G::NCHUNK;
        if (chunk == 0) {
#pragma unroll
            for (int mt = 0; mt < 2; mt++)
#pragma unroll
                for (int nt = 0; nt < G::NT; nt++)
#pragma unroll
                    for (int q = 0; q < 4; q++) acc[mt][nt][q] = 0.0f;
        }

        uint32_t sb_ahi = sb + G::A_BASE + (uint32_t)buf * G::A_BUF;
        uint32_t sb_alo = sb_ahi + (uint32_t)G::A_HALF;
        uint32_t sb_bhi = sb + (uint32_t)(chunk * 2 + 0) * BT;
        uint32_t sb_blo = sb + (uint32_t)(chunk * 2 + 1) * BT;

#pragma unroll
        for (int ks = 0; ks < 8; ks++) {
            int k = ks * 16;
            uint32_t ahi[2][4], alo[2][4];
#pragma unroll
            for (int mt = 0; mt < 2; mt++) {
                uint32_t eoff = (uint32_t)((mi * 32 + mt * 16 + arow_l) * LDAe + k + acol_l) * 2;
                ldsm4(ahi[mt][0], ahi[mt][1], ahi[mt][2], ahi[mt][3], sb_ahi + eoff);
                ldsm4(alo[mt][0], alo[mt][1], alo[mt][2], alo[mt][3], sb_alo + eoff);
            }
            uint32_t bhi[G::NT][2], blo[G::NT][2];
#pragma unroll
            for (int t = 0; t < G::NT / 2; t++) {
                uint32_t eoff = (uint32_t)((ni * G::COLS + t * 16 + brow_l) * LDAe + k + bcol_l) * 2;
                ldsm4(bhi[2*t][0], bhi[2*t][1], bhi[2*t+1][0], bhi[2*t+1][1], sb_bhi + eoff);
                ldsm4(blo[2*t][0], blo[2*t][1], blo[2*t+1][0], blo[2*t+1][1], sb_blo + eoff);
            }
#pragma unroll
            for (int mt = 0; mt < 2; mt++)
#pragma unroll
                for (int nt = 0; nt < G::NT; nt++) {
                    mma16816(acc[mt][nt], ahi[mt], bhi[nt]);
                    mma16816(acc[mt][nt], alo[mt], bhi[nt]);
                    mma16816(acc[mt][nt], ahi[mt], blo[nt]);
                }
        }

        if (chunk == G::NCHUNK - 1) {
            size_t aBase = (size_t)myT[u / G::NCHUNK] * MT;
#pragma unroll
            for (int mt = 0; mt < 2; mt++) {
                size_t row0 = aBase + mi * 32 + mt * 16 + (lane >> 2);
#pragma unroll
                for (int nt = 0; nt < G::NT; nt++) {
                    int col = ni * G::COLS + nt * 8 + ((lane & 3) << 1);
                    *(float2*)&g_Y[row0 * 128 + col]       = make_float2(acc[mt][nt][0], acc[mt][nt][1]);
                    *(float2*)&g_Y[(row0 + 8) * 128 + col] = make_float2(acc[mt][nt][2], acc[mt][nt][3]);
                }
            }
        }
        __syncthreads();
    }
}

// ---------------- 3) layer-1 aggregation (reads g_Y) --------------------------
#define SM_HS_F2   (513 * 32)
#define SM_CNT_OFF (SM_HS_F2 * 8)
#define SM_LST_OFF (SM_CNT_OFF + 512 * 4)
#define AGG_SMEM   (SM_LST_OFF + 512 * PAD * 2)

__global__ void __launch_bounds__(1024) agg_kernel(const float* __restrict__ bias) {
    extern __shared__ char smem[];
    float2* hs   = (float2*)smem;
    int*    scnt = (int*)(smem + SM_CNT_OFF);
    u16*    sl   = (u16*)(smem + SM_LST_OFF);

    int b  = blockIdx.x;
    int ch = blockIdx.y;
    int tid = threadIdx.x;

    const float2* Y2 = (const float2*)g_Y;

    for (int i = tid; i < SS * 32; i += 1024) {
        int t = i >> 5, f = i & 31;
        hs[i] = Y2[((size_t)(b * SS + t)) * 64 + ch * 32 + f];
    }
    if (tid < 32) hs[SS * 32 + tid] = make_float2(0.0f, 0.0f);
    if (tid < SS) scnt[tid] = g_cnt[b * SS + tid];
    {
        const int4* src = (const int4*)(g_nbr + (size_t)b * SS * PAD);
        int4* dst = (int4*)sl;
        for (int i = tid; i < SS * PAD / 8; i += 1024) dst[i] = src[i];
    }
    __syncthreads();

    int lane = tid & 31, warp = tid >> 5;
    float2 bv = ((const float2*)bias)[ch * 32 + lane];
    float bx = 2.0f * bv.x, by = 2.0f * bv.y;
    const float2* hl = hs + lane;

    for (int s = warp; s < SS; s += 32) {
        int row = b * SS + s;
        ull a0 = *(const ull*)&hl[s * 32];
        ull a1 = 0, a2 = 0, a3 = 0, a4 = 0, a5 = 0, a6 = 0, a7 = 0;

        int n8 = scnt[s];
        const u16* L = sl + s * PAD;
        for (int k = 0; k < n8; k += 8) {
            int4 pk = *(const int4*)(L + k);
            int i0 = pk.x & 0xFFFF, i1 = ((unsigned)pk.x) >> 16;
            int i2 = pk.y & 0xFFFF, i3 = ((unsigned)pk.y) >> 16;
            int i4 = pk.z & 0xFFFF, i5 = ((unsigned)pk.z) >> 16;
            int i6 = pk.w & 0xFFFF, i7 = ((unsigned)pk.w) >> 16;
            ull v0 = *(const ull*)&hl[i0];
            ull v1 = *(const ull*)&hl[i1];
            ull v2 = *(const ull*)&hl[i2];
            ull v3 = *(const ull*)&hl[i3];
            ull v4 = *(const ull*)&hl[i4];
            ull v5 = *(const ull*)&hl[i5];
            ull v6 = *(const ull*)&hl[i6];
            ull v7 = *(const ull*)&hl[i7];
            fadd2(a0, v0); fadd2(a1, v1); fadd2(a2, v2); fadd2(a3, v3);
            fadd2(a4, v4); fadd2(a5, v5); fadd2(a6, v6); fadd2(a7, v7);
        }
        fadd2(a0, a1); fadd2(a2, a3); fadd2(a4, a5); fadd2(a6, a7);
        fadd2(a0, a2); fadd2(a4, a6); fadd2(a0, a4);
        float sx, sy; unpack2(a0, sx, sy);
        float di = g_dinv[row];
        float ox = fmaxf((sx + bx) * di, 0.0f);
        float oy = fmaxf((sy + by) * di, 0.0f);
        size_t o = (size_t)row * 64 + ch * 32 + lane;   // buf0
        __nv_bfloat162 hp = __floats2bfloat162_rn(ox, oy);
        float lx = ox - __bfloat162float(__low2bfloat16(hp));
        float ly = oy - __bfloat162float(__high2bfloat16(hp));
        __nv_bfloat162 lp = __floats2bfloat162_rn(lx, ly);
        ((unsigned*)g_ahi)[o] = *(unsigned*)&hp;
        ((unsigned*)g_alo)[o] = *(unsigned*)&lp;
    }
}

// ---------------- 4) fused GEMM + AGG (layers 2,3) ----------------------------
// CTA = (batch b, feature-chunk ch). 1024 threads: warps 0-15 = mma consumers,
// warps 16-31 = cp.async loaders. GEMM Y tile (512x64) written directly to smem
// hs[]; agg runs in the same kernel. XOR-swizzled bf16 tiles (no pitch pad).
// smem: hs 131328 | Whi 16384 | Wlo 16384 | A 2x(hi16384+lo16384) | counts 2048
#define FS_WHI 131328
#define FS_WLO 147712
#define FS_A   164096
#define FS_CNT 229632
#define FUSED_SMEM 231680

template <bool LAST>
__global__ void __launch_bounds__(1024, 1) fused_kernel(
    const u16* __restrict__ ahi, const u16* __restrict__ alo,
    unsigned* __restrict__ ohi, unsigned* __restrict__ olo,
    const u16* __restrict__ whi, const u16* __restrict__ wlo,
    const float* __restrict__ bias, const float* __restrict__ Wp,
    float* __restrict__ out)
{
    extern __shared__ char smem[];
    uint32_t sb = smem_to_u32(smem);
    int b = blockIdx.x, ch = blockIdx.y;
    int tid = threadIdx.x, wid = tid >> 5, lane = tid & 31;
    int rowBase = b * SS;
    float2* hs = (float2*)smem;
    int* scnt = (int*)(smem + FS_CNT);
    u16* sl = (u16*)(smem + FS_A);

    bool loader = (wid >= 16);
    int lt = tid & 511;

    if (loader) {
        // W rows ch*64..ch*64+63, K=128, hi+lo, XOR-swizzled
        for (int i = lt; i < 1024; i += 512) {
            int r = i >> 4, c = i & 15;
            uint32_t doff = (uint32_t)(r * 256) + (uint32_t)((c ^ (r & 15)) << 4);
            size_t src = (size_t)(ch * 64 + r) * 128 + c * 8;
            cp_async16(sb + FS_WHI + doff, whi + src);
            cp_async16(sb + FS_WLO + doff, wlo + src);
        }
        if (lt < 128) cp_async16(sb + FS_CNT + lt * 16, (const char*)(g_cnt + rowBase) + lt * 16);
        // A chunk 0 (rows 0..63)
        for (int i = lt; i < 1024; i += 512) {
            int r = i >> 4, c = i & 15;
            uint32_t doff = (uint32_t)(r * 256) + (uint32_t)((c ^ (r & 15)) << 4);
            size_t src = ((size_t)(rowBase + r)) * 128 + c * 8;
            cp_async16(sb + FS_A + doff, ahi + src);
            cp_async16(sb + FS_A + 16384 + doff, alo + src);
        }
        CP_COMMIT(); CP_WAIT0();
        if (lt < 64) ((float*)smem)[512 * 64 + lt] = 0.0f;    // hs dummy row 512
    }
    __syncthreads();

    for (int g = 0; g < 8; g++) {
        if (loader) {
            if (g < 7) {
                int gg = g + 1;
                uint32_t dbase = sb + FS_A + (uint32_t)(gg & 1) * 32768;
                for (int i = lt; i < 1024; i += 512) {
                    int r = i >> 4, c = i & 15;
                    uint32_t doff = (uint32_t)(r * 256) + (uint32_t)((c ^ (r & 15)) << 4);
                    size_t src = ((size_t)(rowBase + gg * 64 + r)) * 128 + c * 8;
                    cp_async16(dbase + doff, ahi + src);
                    cp_async16(dbase + 16384 + doff, alo + src);
                }
            } else {
                // lists part 0 into buf0 (free since chunk 6 consumed)
                const char* lsrc = (const char*)(g_nbr + (size_t)rowBase * PAD);
                for (int i = lt; i < 2048; i += 512)
                    cp_async16(sb + FS_A + i * 16, lsrc + i * 16);
            }
            CP_COMMIT(); CP_WAIT0();
        } else {
            int mi = wid & 3, ni = wid >> 2;
            uint32_t sbh = sb + FS_A + (uint32_t)(g & 1) * 32768;
            uint32_t sbl = sbh + 16384;
            float acc0[4] = {0, 0, 0, 0}, acc1[4] = {0, 0, 0, 0};
            int ar = mi * 16 + (lane & 15);
            int arx = ar & 15;
            int br = ni * 16 + (lane & 7) + ((lane >> 4) << 3);
            int brx = br & 15;
            uint32_t arow_off = (uint32_t)ar * 256;
            uint32_t brow_off = (uint32_t)br * 256;
            int ac_base = lane >> 4;
            int bc_base = (lane >> 3) & 1;
#pragma unroll
            for (int ks = 0; ks < 8; ks++) {
                uint32_t aoff = arow_off + (uint32_t)(((2 * ks + ac_base) ^ arx) << 4);
                uint32_t boff = brow_off + (uint32_t)(((2 * ks + bc_base) ^ brx) << 4);
                uint32_t a_hi[4], a_lo[4], b_hi[4], b_lo[4];
                ldsm4(a_hi[0], a_hi[1], a_hi[2], a_hi[3], sbh + aoff);
                ldsm4(a_lo[0], a_lo[1], a_lo[2], a_lo[3], sbl + aoff);
                ldsm4(b_hi[0], b_hi[1], b_hi[2], b_hi[3], sb + FS_WHI + boff);
                ldsm4(b_lo[0], b_lo[1], b_lo[2], b_lo[3], sb + FS_WLO + boff);
                mma16816(acc0, a_hi, b_hi);
                mma16816(acc0, a_lo, b_hi);
                mma16816(acc0, a_hi, b_lo);
                mma16816(acc1, a_hi, b_hi + 2);
                mma16816(acc1, a_lo, b_hi + 2);
                mma16816(acc1, a_hi, b_lo + 2);
            }
            // epilogue: write Y directly into hs
            int t0 = g * 64 + mi * 16 + (lane >> 2);
            int f0 = ni * 8 + (lane & 3);
            hs[t0 * 32 + f0]           = make_float2(acc0[0], acc0[1]);
            hs[(t0 + 8) * 32 + f0]     = make_float2(acc0[2], acc0[3]);
            hs[t0 * 32 + f0 + 4]       = make_float2(acc1[0], acc1[1]);
            hs[(t0 + 8) * 32 + f0 + 4] = make_float2(acc1[2], acc1[3]);
        }
        __syncthreads();
    }
    // lists part 1 into buf1 (chunk 7 consumed)
    if (loader) {
        const char* lsrc = (const char*)(g_nbr + (size_t)rowBase * PAD) + 32768;
        for (int i = lt; i < 2048; i += 512)
            cp_async16(sb + FS_A + 32768 + i * 16, lsrc + i * 16);
        CP_COMMIT(); CP_WAIT0();
    }
    __syncthreads();

    // ---- AGG phase (all 32 warps)
    float2 bv = ((const float2*)bias)[ch * 32 + lane];
    float bx = 2.0f * bv.x, by = 2.0f * bv.y;
    const float2* hl = hs + lane;
    float mx = 0.0f, my = 0.0f;

    for (int s = wid; s < SS; s += 32) {
        int row = rowBase + s;
        ull a0 = *(const ull*)&hl[s * 32];
        ull a1 = 0, a2 = 0, a3 = 0, a4 = 0, a5 = 0, a6 = 0, a7 = 0;

        int n8 = scnt[s];
        const u16* L = sl + s * PAD;
        for (int k = 0; k < n8; k += 8) {
            int4 pk = *(const int4*)(L + k);
            int i0 = pk.x & 0xFFFF, i1 = ((unsigned)pk.x) >> 16;
            int i2 = pk.y & 0xFFFF, i3 = ((unsigned)pk.y) >> 16;
            int i4 = pk.z & 0xFFFF, i5 = ((unsigned)pk.z) >> 16;
            int i6 = pk.w & 0xFFFF, i7 = ((unsigned)pk.w) >> 16;
            ull v0 = *(const ull*)&hl[i0];
            ull v1 = *(const ull*)&hl[i1];
            ull v2 = *(const ull*)&hl[i2];
            ull v3 = *(const ull*)&hl[i3];
            ull v4 = *(const ull*)&hl[i4];
            ull v5 = *(const ull*)&hl[i5];
            ull v6 = *(const ull*)&hl[i6];
            ull v7 = *(const ull*)&hl[i7];
            fadd2(a0, v0); fadd2(a1, v1); fadd2(a2, v2); fadd2(a3, v3);
            fadd2(a4, v4); fadd2(a5, v5); fadd2(a6, v6); fadd2(a7, v7);
        }
        fadd2(a0, a1); fadd2(a2, a3); fadd2(a4, a5); fadd2(a6, a7);
        fadd2(a0, a2); fadd2(a4, a6); fadd2(a0, a4);
        float sx, sy; unpack2(a0, sx, sy);
        float di = g_dinv[row];
        float ox = fmaxf((sx + bx) * di, 0.0f);
        float oy = fmaxf((sy + by) * di, 0.0f);
        if (LAST) {
            mx = fmaxf(mx, ox);
            my = fmaxf(my, oy);
        } else {
            size_t o = (size_t)row * 64 + ch * 32 + lane;
            __nv_bfloat162 hp = __floats2bfloat162_rn(ox, oy);
            float lx = ox - __bfloat162float(__low2bfloat16(hp));
            float ly = oy - __bfloat162float(__high2bfloat16(hp));
            __nv_bfloat162 lp = __floats2bfloat162_rn(lx, ly);
            ohi[o] = *(unsigned*)&hp;
            olo[o] = *(unsigned*)&lp;
        }
    }

    if (LAST) {
        __syncthreads();
        float* red = (float*)(smem + FS_A);     // lists done; reuse
        red[wid * 64 + lane * 2]     = mx;
        red[wid * 64 + lane * 2 + 1] = my;
        __syncthreads();
        if (wid == 0) {
            float m0 = 0.0f, m1 = 0.0f;
#pragma unroll
            for (int w = 0; w < 32; w++) {
                m0 = fmaxf(m0, red[w * 64 + lane * 2]);
                m1 = fmaxf(m1, red[w * 64 + lane * 2 + 1]);
            }
            int j0 = ch * 64 + lane * 2;
            float p0 = m0 * Wp[0 * 128 + j0] + m1 * Wp[0 * 128 + j0 + 1];
            float p1 = m0 * Wp[1 * 128 + j0] + m1 * Wp[1 * 128 + j0 + 1];
#pragma unroll
            for (int off = 16; off > 0; off >>= 1) {
                p0 += __shfl_down_sync(0xFFFFFFFFu, p0, off);
                p1 += __shfl_down_sync(0xFFFFFFFFu, p1, off);
            }
            if (lane == 0) {
                atomicAdd(&out[b * 2 + 0], p0);
                atomicAdd(&out[b * 2 + 1], p1);
            }
        }
    }
}

// ---------------- launcher ---------------------------------------------------
extern "C" void kernel_launch(void* const* d_in, const int* in_sizes, int n_in,
                              void* d_out, int out_size) {
    const int*   sent = (const int*)  d_in[0];
    const float* adj  = (const float*)d_in[1];
    const float* emb  = (const float*)d_in[2];
    const float* W1   = (const float*)d_in[3];
    const float* b1   = (const float*)d_in[4];
    const float* W2   = (const float*)d_in[5];
    const float* b2   = (const float*)d_in[6];
    const float* W3   = (const float*)d_in[7];
    const float* b3   = (const float*)d_in[8];
    const float* Wp   = (const float*)d_in[9];
    const float* bp   = (const float*)d_in[10];
    float* out = (float*)d_out;

    cudaFuncSetAttribute(agg_kernel, cudaFuncAttributeMaxDynamicSharedMemorySize, AGG_SMEM);
    cudaFuncSetAttribute((const void*)pgemm_kernel<EE, 64>,
                         cudaFuncAttributeMaxDynamicSharedMemorySize, GS<EE, 64>::TOTAL);
    cudaFuncSetAttribute((const void*)fused_kernel<false>,
                         cudaFuncAttributeMaxDynamicSharedMemorySize, FUSED_SMEM);
    cudaFuncSetAttribute((const void*)fused_kernel<true>,
                         cudaFuncAttributeMaxDynamicSharedMemorySize, FUSED_SMEM);

    u16 *whi_d, *wlo_d, *ahi_d, *alo_d;
    cudaGetSymbolAddress((void**)&whi_d, g_whi);
    cudaGetSymbolAddress((void**)&wlo_d, g_wlo);
    cudaGetSymbolAddress((void**)&ahi_d, g_ahi);
    cudaGetSymbolAddress((void**)&alo_d, g_alo);
    u16* ahi1 = ahi_d + (size_t)MM * 128;
    u16* alo1 = alo_d + (size_t)MM * 128;

    prep_kernel<<<PREP_GRID, 256>>>(sent, (const float4*)emb, adj, W1, W2, W3, bp, out);

    // layer 1: persistent GEMM (K=256) + agg -> buf0
    pgemm_kernel<EE, 64><<<PGRID, 512, GS<EE, 64>::TOTAL>>>(whi_d, wlo_d);
    agg_kernel<<<dim3(BB, 2), 1024, AGG_SMEM>>>(b1);

    // layer 2: fused GEMM+agg, buf0 -> buf1
    fused_kernel<false><<<dim3(BB, 2), 1024, FUSED_SMEM>>>(
        ahi_d, alo_d, (unsigned*)ahi1, (unsigned*)alo1,
        whi_d + W2_OFF, wlo_d + W2_OFF, b2, nullptr, nullptr);

    // layer 3: fused GEMM+agg+pool+logits, buf1 -> out
    fused_kernel<true><<<dim3(BB, 2), 1024, FUSED_SMEM>>>(
        ahi1, alo1, nullptr, nullptr,
        whi_d + W3_OFF, wlo_d + W3_OFF, b3, Wp, out);
}